// round 2
// baseline (speedup 1.0000x reference)
#include <cuda_runtime.h>
#include <cuda_bf16.h>
#include <cstdint>

// Problem constants
#define NS 2048      // sequence length
#define ND 1024      // model dim
#define NH 16        // heads
#define NHD 64       // head dim
#define NK 64        // neighbors per token

// ---------------------------------------------------------------------------
// Scratch (static device allocations — no cudaMalloc allowed)
// ---------------------------------------------------------------------------
__device__ float g_h[NS * ND];        // h = x @ W_in^T
__device__ float g_fused[NS * ND];    // attention output
__device__ int   g_routes[NS * NK];   // normalized int32 routes

// ---------------------------------------------------------------------------
// Route normalization: input may be int64 (reference declares int64) or int32
// (jax default x64-disabled silently downcasts). Detect by sniffing odd 32-bit
// words of the first 512 entries: all zero => int64 little-endian high words.
// ---------------------------------------------------------------------------
__global__ void prep_routes_kernel(const unsigned* __restrict__ src,
                                   int* __restrict__ dst, int n) {
    int any = 0;
    for (int i = threadIdx.x; i < 512; i += blockDim.x)
        if (src[2 * i + 1] != 0u) any = 1;
    any = __syncthreads_or(any);

    int stride = gridDim.x * blockDim.x;
    int start = blockIdx.x * blockDim.x + threadIdx.x;
    if (any) {  // int32 layout
        for (int i = start; i < n; i += stride) dst[i] = (int)src[i];
    } else {    // int64 layout: take low words
        for (int i = start; i < n; i += stride) dst[i] = (int)src[2 * i];
    }
}

// ---------------------------------------------------------------------------
// TF32 helpers
// ---------------------------------------------------------------------------
__device__ __forceinline__ float to_tf32(float x) {
    uint32_t r;
    asm("cvt.rna.tf32.f32 %0, %1;" : "=r"(r) : "f"(x));
    return __uint_as_float(r);
}

__device__ __forceinline__ void mma_tf32(float* c, const uint32_t* a, const uint32_t* b) {
    asm volatile(
        "mma.sync.aligned.m16n8k8.row.col.f32.tf32.tf32.f32 "
        "{%0,%1,%2,%3}, {%4,%5,%6,%7}, {%8,%9}, {%0,%1,%2,%3};\n"
        : "+f"(c[0]), "+f"(c[1]), "+f"(c[2]), "+f"(c[3])
        : "r"(a[0]), "r"(a[1]), "r"(a[2]), "r"(a[3]),
          "r"(b[0]), "r"(b[1]));
}

// ---------------------------------------------------------------------------
// GEMM: C[M,N] = A[M,Kd] @ B[N,Kd]^T  (both row-major, K contiguous => row.col)
// EPI: C += bias[n] + resid[m,n]
// Tiles: BM=64, BN=64, BK=16. 128 threads = 4 warps in 2x2, warp tile 32x32
// (2x4 grid of m16n8k8 MMAs, 2 k-substeps per tile).
// ---------------------------------------------------------------------------
template <bool EPI>
__global__ void gemm_tf32_kernel(const float* __restrict__ A,
                                 const float* __restrict__ B,
                                 float* __restrict__ C,
                                 const float* __restrict__ bias,
                                 const float* __restrict__ resid,
                                 int M, int N, int Kd) {
    constexpr int BM = 64, BN = 64, BK = 16, LDSZ = BK + 1;
    __shared__ float As[BM * LDSZ];
    __shared__ float Bs[BN * LDSZ];

    const int tid = threadIdx.x;
    const int w = tid >> 5, l = tid & 31;
    const int wm = w >> 1, wn = w & 1;   // 2x2 warp grid
    const int g = l >> 2, t = l & 3;     // groupID, threadInGroup
    const int bm = blockIdx.y * BM, bn = blockIdx.x * BN;

    float acc[2][4][4];
#pragma unroll
    for (int mi = 0; mi < 2; mi++)
#pragma unroll
        for (int nj = 0; nj < 4; nj++)
#pragma unroll
            for (int q = 0; q < 4; q++) acc[mi][nj][q] = 0.f;

    for (int k0 = 0; k0 < Kd; k0 += BK) {
#pragma unroll
        for (int i = 0; i < 8; i++) {
            int idx = tid + i * 128;
            int r = idx >> 4, c = idx & 15;
            As[r * LDSZ + c] = to_tf32(A[(size_t)(bm + r) * Kd + k0 + c]);
            Bs[r * LDSZ + c] = to_tf32(B[(size_t)(bn + r) * Kd + k0 + c]);
        }
        __syncthreads();

#pragma unroll
        for (int kk = 0; kk < BK; kk += 8) {
            uint32_t a[2][4], b[4][2];
#pragma unroll
            for (int mi = 0; mi < 2; mi++) {
                int r = wm * 32 + mi * 16 + g;
                a[mi][0] = __float_as_uint(As[r * LDSZ + kk + t]);
                a[mi][1] = __float_as_uint(As[(r + 8) * LDSZ + kk + t]);
                a[mi][2] = __float_as_uint(As[r * LDSZ + kk + t + 4]);
                a[mi][3] = __float_as_uint(As[(r + 8) * LDSZ + kk + t + 4]);
            }
#pragma unroll
            for (int nj = 0; nj < 4; nj++) {
                int cc = wn * 32 + nj * 8 + g;
                b[nj][0] = __float_as_uint(Bs[cc * LDSZ + kk + t]);
                b[nj][1] = __float_as_uint(Bs[cc * LDSZ + kk + t + 4]);
            }
#pragma unroll
            for (int mi = 0; mi < 2; mi++)
#pragma unroll
                for (int nj = 0; nj < 4; nj++)
                    mma_tf32(acc[mi][nj], a[mi], b[nj]);
        }
        __syncthreads();
    }

    // Epilogue: c0 (row, col), c1 (row, col+1), c2 (row+8, col), c3 (row+8, col+1)
#pragma unroll
    for (int mi = 0; mi < 2; mi++) {
#pragma unroll
        for (int nj = 0; nj < 4; nj++) {
            int row = bm + wm * 32 + mi * 16 + g;
            int col = bn + wn * 32 + nj * 8 + 2 * t;
            float v0 = acc[mi][nj][0], v1 = acc[mi][nj][1];
            float v2 = acc[mi][nj][2], v3 = acc[mi][nj][3];
            if (EPI) {
                float b0 = bias[col], b1 = bias[col + 1];
                v0 += b0 + resid[(size_t)row * N + col];
                v1 += b1 + resid[(size_t)row * N + col + 1];
                v2 += b0 + resid[(size_t)(row + 8) * N + col];
                v3 += b1 + resid[(size_t)(row + 8) * N + col + 1];
            }
            *(float2*)&C[(size_t)row * N + col] = make_float2(v0, v1);
            *(float2*)&C[(size_t)(row + 8) * N + col] = make_float2(v2, v3);
        }
    }
}

// ---------------------------------------------------------------------------
// Fused gather-attention.
// Block = (token s, group of GH=4 heads). 128 threads = 4 warps, warp per head.
// 1) gather K=64 neighbor slices (4 heads x 64 = 256 floats each) into smem
//    (stride 258 so that phase-1's k-major reads are only 2-way conflicted)
// 2) scores: lane L computes k=L and k=L+32 (full 64-dot each, q broadcast)
// 3) warp softmax over 64 scores (2 per lane)
// 4) fused: lane L owns dims (2L, 2L+1), accumulates over k from smem
// Single L2 pass over the 512 MB gather footprint.
// ---------------------------------------------------------------------------
#define GH 4
#define VSTRIDE (GH * NHD + 2)   // 258 floats per k-row
#define ATTN_SMEM_BYTES ((NK * VSTRIDE + GH * NHD + GH * NK) * 4 + NK * 4)

__global__ void attn_kernel(const float* __restrict__ h,
                            const int* __restrict__ routes,
                            float* __restrict__ fused) {
    extern __shared__ float sm[];
    float* vs = sm;                       // [NK][VSTRIDE]
    float* qs = vs + NK * VSTRIDE;        // [GH*NHD]
    float* ws = qs + GH * NHD;            // [GH][NK]
    int* rt = (int*)(ws + GH * NK);       // [NK]

    const int s = blockIdx.x;
    const int g0 = blockIdx.y * GH;       // first head of this group
    const int tid = threadIdx.x;
    const int w = tid >> 5, l = tid & 31;

    if (tid < NK) rt[tid] = routes[s * NK + tid];
    {   // q slice: 256 floats, float2 per thread
        const float2* qsrc = (const float2*)(h + (size_t)s * ND + g0 * NHD);
        ((float2*)qs)[tid] = qsrc[tid];
    }
    __syncthreads();

    // ---- gather: warp w handles k = w, w+4, ... (each k-row = 256 floats) ----
    for (int k = w; k < NK; k += 4) {
        const float4* src = (const float4*)(h + (size_t)rt[k] * ND + g0 * NHD);
        float* dst = vs + k * VSTRIDE;
#pragma unroll
        for (int i = 0; i < 2; i++) {
            float4 v = src[l + 32 * i];
            int d = (l + 32 * i) * 4;
            *(float2*)(dst + d) = make_float2(v.x, v.y);
            *(float2*)(dst + d + 2) = make_float2(v.z, v.w);
        }
    }
    __syncthreads();

    // ---- scores (warp w == head w of the group) ----
    const float* qh = qs + w * NHD;
    const float* v0p = vs + l * VSTRIDE + w * NHD;
    const float* v1p = vs + (l + 32) * VSTRIDE + w * NHD;
    float sc0 = 0.f, sc1 = 0.f;
#pragma unroll
    for (int d = 0; d < NHD; d += 2) {
        float q0 = qh[d], q1 = qh[d + 1];
        float2 a = *(const float2*)(v0p + d);
        float2 b = *(const float2*)(v1p + d);
        sc0 += q0 * a.x + q1 * a.y;
        sc1 += q0 * b.x + q1 * b.y;
    }
    const float scale = 0.125f;  // 1/sqrt(64)
    sc0 *= scale; sc1 *= scale;

    // ---- softmax over 64 (2 per lane) ----
    float mx = fmaxf(sc0, sc1);
#pragma unroll
    for (int o = 16; o; o >>= 1) mx = fmaxf(mx, __shfl_xor_sync(0xffffffffu, mx, o));
    float e0 = __expf(sc0 - mx), e1 = __expf(sc1 - mx);
    float sum = e0 + e1;
#pragma unroll
    for (int o = 16; o; o >>= 1) sum += __shfl_xor_sync(0xffffffffu, sum, o);
    float inv = 1.0f / sum;
    ws[w * NK + l] = e0 * inv;
    ws[w * NK + l + 32] = e1 * inv;
    __syncwarp();

    // ---- weighted sum: lane l owns dims (2l, 2l+1) of head w ----
    float ax = 0.f, ay = 0.f;
    const float* col = vs + w * NHD + 2 * l;
    const float* wr = ws + w * NK;
#pragma unroll
    for (int k = 0; k < NK; k++) {
        float wk = wr[k];
        float2 v = *(const float2*)(col + k * VSTRIDE);
        ax += wk * v.x;
        ay += wk * v.y;
    }
    *(float2*)(fused + (size_t)s * ND + (g0 + w) * NHD + 2 * l) = make_float2(ax, ay);
}

// ---------------------------------------------------------------------------
// Launch
// ---------------------------------------------------------------------------
extern "C" void kernel_launch(void* const* d_in, const int* in_sizes, int n_in,
                              void* d_out, int out_size) {
    const float* x     = (const float*)d_in[0];
    const unsigned* rt = (const unsigned*)d_in[1];
    const float* W_in  = (const float*)d_in[2];
    const float* W_out = (const float*)d_in[3];
    const float* b_out = (const float*)d_in[4];
    float* out = (float*)d_out;

    float* hbuf;  float* fbuf;  int* rbuf;
    cudaGetSymbolAddress((void**)&hbuf, g_h);
    cudaGetSymbolAddress((void**)&fbuf, g_fused);
    cudaGetSymbolAddress((void**)&rbuf, g_routes);

    cudaFuncSetAttribute(attn_kernel, cudaFuncAttributeMaxDynamicSharedMemorySize,
                         ATTN_SMEM_BYTES);

    // 1) normalize routes
    prep_routes_kernel<<<64, 256>>>(rt, rbuf, NS * NK);

    // 2) h = x @ W_in^T
    dim3 gemm_grid(ND / 64, NS / 64);  // (16, 32)
    gemm_tf32_kernel<false><<<gemm_grid, 128>>>(x, W_in, hbuf, nullptr, nullptr,
                                                NS, ND, ND);

    // 3) gather attention
    attn_kernel<<<dim3(NS, NH / GH), 128, ATTN_SMEM_BYTES>>>(hbuf, rbuf, fbuf);

    // 4) out = fused @ W_out^T + b_out + x
    gemm_tf32_kernel<true><<<gemm_grid, 128>>>(fbuf, W_out, out, b_out, x,
                                               NS, ND, ND);
}

// round 3
// speedup vs baseline: 1.3324x; 1.3324x over previous
#include <cuda_runtime.h>
#include <cuda_bf16.h>
#include <cstdint>

// Problem constants
#define NS 2048      // sequence length
#define ND 1024      // model dim
#define NH 16        // heads
#define NHD 64       // head dim
#define NK 64        // neighbors per token

// ---------------------------------------------------------------------------
// Scratch (static device allocations — no cudaMalloc allowed)
// ---------------------------------------------------------------------------
__device__ float g_h[NS * ND];        // h = x @ W_in^T
__device__ float g_fused[NS * ND];    // attention output
__device__ int   g_routes[NS * NK];   // normalized int32 routes

// ---------------------------------------------------------------------------
// Route normalization: int64 (reference) or int32 (jax x64 off). Sniff odd
// 32-bit words of the first 512 entries: all zero => int64 little-endian.
// ---------------------------------------------------------------------------
__global__ void prep_routes_kernel(const unsigned* __restrict__ src,
                                   int* __restrict__ dst, int n) {
    int any = 0;
    for (int i = threadIdx.x; i < 512; i += blockDim.x)
        if (src[2 * i + 1] != 0u) any = 1;
    any = __syncthreads_or(any);

    int stride = gridDim.x * blockDim.x;
    int start = blockIdx.x * blockDim.x + threadIdx.x;
    if (any) {
        for (int i = start; i < n; i += stride) dst[i] = (int)src[i];
    } else {
        for (int i = start; i < n; i += stride) dst[i] = (int)src[2 * i];
    }
}

// ---------------------------------------------------------------------------
// MMA + cp.async helpers
// ---------------------------------------------------------------------------
__device__ __forceinline__ void mma_tf32(float* c, const uint32_t* a, const uint32_t* b) {
    asm volatile(
        "mma.sync.aligned.m16n8k8.row.col.f32.tf32.tf32.f32 "
        "{%0,%1,%2,%3}, {%4,%5,%6,%7}, {%8,%9}, {%0,%1,%2,%3};\n"
        : "+f"(c[0]), "+f"(c[1]), "+f"(c[2]), "+f"(c[3])
        : "r"(a[0]), "r"(a[1]), "r"(a[2]), "r"(a[3]),
          "r"(b[0]), "r"(b[1]));
}

__device__ __forceinline__ void cp_async16(void* smem_ptr, const void* gmem_ptr) {
    uint32_t s = (uint32_t)__cvta_generic_to_shared(smem_ptr);
    asm volatile("cp.async.cg.shared.global [%0], [%1], 16;\n" :: "r"(s), "l"(gmem_ptr));
}
__device__ __forceinline__ void cp_commit() {
    asm volatile("cp.async.commit_group;\n");
}
template <int N>
__device__ __forceinline__ void cp_wait() {
    asm volatile("cp.async.wait_group %0;\n" :: "n"(N));
}

// ---------------------------------------------------------------------------
// GEMM: C[M,N] = A[M,Kd] @ B[N,Kd]^T (row-major, K contiguous => row.col MMA)
// EPI: C += bias[n] + resid[m,n]
// BM=BN=128, BK=16. 256 threads = 8 warps (2 x 4), warp tile 64x32
// (4x4 grid of m16n8k8, 2 k-substeps). cp.async 2-stage double buffer.
// Raw fp32 fed to tf32 MMA (HW truncates mantissa; no cvt needed).
// smem row stride 20 floats: 16B-aligned for cp.async, and fragment reads
// (bank = (g*20+t) mod 32 over g=0..7,t=0..3) are conflict-free.
// ---------------------------------------------------------------------------
template <bool EPI>
__global__ __launch_bounds__(256) void gemm_tf32_kernel(
        const float* __restrict__ A, const float* __restrict__ B,
        float* __restrict__ C, const float* __restrict__ bias,
        const float* __restrict__ resid, int M, int N, int Kd) {
    constexpr int BM = 128, BN = 128, BK = 16, LDA = BK + 4;  // 20 floats/row
    __shared__ float As[2][BM * LDA];
    __shared__ float Bs[2][BN * LDA];

    const int tid = threadIdx.x;
    const int w = tid >> 5, l = tid & 31;
    const int wm = w >> 2, wn = w & 3;   // 2 x 4 warp grid
    const int g = l >> 2, t = l & 3;     // groupID, threadInGroup
    const int bm = blockIdx.y * BM, bn = blockIdx.x * BN;

    // staging indices: 512 float4 per matrix per stage, 2 per thread
    const int r0 = (tid + 0) >> 2,   c0 = ((tid + 0) & 3) * 4;
    const int r1 = (tid + 256) >> 2, c1 = ((tid + 256) & 3) * 4;

    float acc[4][4][4];
#pragma unroll
    for (int mi = 0; mi < 4; mi++)
#pragma unroll
        for (int nj = 0; nj < 4; nj++)
#pragma unroll
            for (int q = 0; q < 4; q++) acc[mi][nj][q] = 0.f;

    const int NIT = Kd / BK;  // 64

    // prologue: stage 0
    {
        const int k0 = 0;
        cp_async16(&As[0][r0 * LDA + c0], &A[(size_t)(bm + r0) * Kd + k0 + c0]);
        cp_async16(&As[0][r1 * LDA + c1], &A[(size_t)(bm + r1) * Kd + k0 + c1]);
        cp_async16(&Bs[0][r0 * LDA + c0], &B[(size_t)(bn + r0) * Kd + k0 + c0]);
        cp_async16(&Bs[0][r1 * LDA + c1], &B[(size_t)(bn + r1) * Kd + k0 + c1]);
        cp_commit();
    }

    for (int it = 0; it < NIT; it++) {
        if (it + 1 < NIT) {
            const int k0 = (it + 1) * BK;
            const int st = (it + 1) & 1;
            cp_async16(&As[st][r0 * LDA + c0], &A[(size_t)(bm + r0) * Kd + k0 + c0]);
            cp_async16(&As[st][r1 * LDA + c1], &A[(size_t)(bm + r1) * Kd + k0 + c1]);
            cp_async16(&Bs[st][r0 * LDA + c0], &B[(size_t)(bn + r0) * Kd + k0 + c0]);
            cp_async16(&Bs[st][r1 * LDA + c1], &B[(size_t)(bn + r1) * Kd + k0 + c1]);
            cp_commit();
            cp_wait<1>();
        } else {
            cp_wait<0>();
        }
        __syncthreads();

        const float* as = As[it & 1];
        const float* bs = Bs[it & 1];
#pragma unroll
        for (int kk = 0; kk < BK; kk += 8) {
            uint32_t a[4][4], b[4][2];
#pragma unroll
            for (int mi = 0; mi < 4; mi++) {
                int r = wm * 64 + mi * 16 + g;
                a[mi][0] = __float_as_uint(as[r * LDA + kk + t]);
                a[mi][1] = __float_as_uint(as[(r + 8) * LDA + kk + t]);
                a[mi][2] = __float_as_uint(as[r * LDA + kk + t + 4]);
                a[mi][3] = __float_as_uint(as[(r + 8) * LDA + kk + t + 4]);
            }
#pragma unroll
            for (int nj = 0; nj < 4; nj++) {
                int cc = wn * 32 + nj * 8 + g;
                b[nj][0] = __float_as_uint(bs[cc * LDA + kk + t]);
                b[nj][1] = __float_as_uint(bs[cc * LDA + kk + t + 4]);
            }
#pragma unroll
            for (int mi = 0; mi < 4; mi++)
#pragma unroll
                for (int nj = 0; nj < 4; nj++)
                    mma_tf32(acc[mi][nj], a[mi], b[nj]);
        }
        __syncthreads();   // stage (it&1) gets overwritten at it+2's prefetch
    }

    // Epilogue
#pragma unroll
    for (int mi = 0; mi < 4; mi++) {
#pragma unroll
        for (int nj = 0; nj < 4; nj++) {
            int row = bm + wm * 64 + mi * 16 + g;
            int col = bn + wn * 32 + nj * 8 + 2 * t;
            float v0 = acc[mi][nj][0], v1 = acc[mi][nj][1];
            float v2 = acc[mi][nj][2], v3 = acc[mi][nj][3];
            if (EPI) {
                float b0 = bias[col], b1 = bias[col + 1];
                v0 += b0 + resid[(size_t)row * N + col];
                v1 += b1 + resid[(size_t)row * N + col + 1];
                v2 += b0 + resid[(size_t)(row + 8) * N + col];
                v3 += b1 + resid[(size_t)(row + 8) * N + col + 1];
            }
            *(float2*)&C[(size_t)row * N + col] = make_float2(v0, v1);
            *(float2*)&C[(size_t)(row + 8) * N + col] = make_float2(v2, v3);
        }
    }
}

// ---------------------------------------------------------------------------
// Fused gather-attention (unchanged from R2 — next optimization target,
// kept fixed this round so the GEMM delta is attributable).
// ---------------------------------------------------------------------------
#define GH 4
#define VSTRIDE (GH * NHD + 2)   // 258 floats per k-row
#define ATTN_SMEM_BYTES ((NK * VSTRIDE + GH * NHD + GH * NK) * 4 + NK * 4)

__global__ void attn_kernel(const float* __restrict__ h,
                            const int* __restrict__ routes,
                            float* __restrict__ fused) {
    extern __shared__ float sm[];
    float* vs = sm;                       // [NK][VSTRIDE]
    float* qs = vs + NK * VSTRIDE;        // [GH*NHD]
    float* ws = qs + GH * NHD;            // [GH][NK]
    int* rt = (int*)(ws + GH * NK);       // [NK]

    const int s = blockIdx.x;
    const int g0 = blockIdx.y * GH;
    const int tid = threadIdx.x;
    const int w = tid >> 5, l = tid & 31;

    if (tid < NK) rt[tid] = routes[s * NK + tid];
    {
        const float2* qsrc = (const float2*)(h + (size_t)s * ND + g0 * NHD);
        ((float2*)qs)[tid] = qsrc[tid];
    }
    __syncthreads();

    for (int k = w; k < NK; k += 4) {
        const float4* src = (const float4*)(h + (size_t)rt[k] * ND + g0 * NHD);
        float* dst = vs + k * VSTRIDE;
#pragma unroll
        for (int i = 0; i < 2; i++) {
            float4 v = src[l + 32 * i];
            int d = (l + 32 * i) * 4;
            *(float2*)(dst + d) = make_float2(v.x, v.y);
            *(float2*)(dst + d + 2) = make_float2(v.z, v.w);
        }
    }
    __syncthreads();

    const float* qh = qs + w * NHD;
    const float* v0p = vs + l * VSTRIDE + w * NHD;
    const float* v1p = vs + (l + 32) * VSTRIDE + w * NHD;
    float sc0 = 0.f, sc1 = 0.f;
#pragma unroll
    for (int d = 0; d < NHD; d += 2) {
        float q0 = qh[d], q1 = qh[d + 1];
        float2 a = *(const float2*)(v0p + d);
        float2 b = *(const float2*)(v1p + d);
        sc0 += q0 * a.x + q1 * a.y;
        sc1 += q0 * b.x + q1 * b.y;
    }
    const float scale = 0.125f;
    sc0 *= scale; sc1 *= scale;

    float mx = fmaxf(sc0, sc1);
#pragma unroll
    for (int o = 16; o; o >>= 1) mx = fmaxf(mx, __shfl_xor_sync(0xffffffffu, mx, o));
    float e0 = __expf(sc0 - mx), e1 = __expf(sc1 - mx);
    float sum = e0 + e1;
#pragma unroll
    for (int o = 16; o; o >>= 1) sum += __shfl_xor_sync(0xffffffffu, sum, o);
    float inv = 1.0f / sum;
    ws[w * NK + l] = e0 * inv;
    ws[w * NK + l + 32] = e1 * inv;
    __syncwarp();

    float ax = 0.f, ay = 0.f;
    const float* col = vs + w * NHD + 2 * l;
    const float* wr = ws + w * NK;
#pragma unroll
    for (int k = 0; k < NK; k++) {
        float wk = wr[k];
        float2 v = *(const float2*)(col + k * VSTRIDE);
        ax += wk * v.x;
        ay += wk * v.y;
    }
    *(float2*)(fused + (size_t)s * ND + (g0 + w) * NHD + 2 * l) = make_float2(ax, ay);
}

// ---------------------------------------------------------------------------
// Launch
// ---------------------------------------------------------------------------
extern "C" void kernel_launch(void* const* d_in, const int* in_sizes, int n_in,
                              void* d_out, int out_size) {
    const float* x     = (const float*)d_in[0];
    const unsigned* rt = (const unsigned*)d_in[1];
    const float* W_in  = (const float*)d_in[2];
    const float* W_out = (const float*)d_in[3];
    const float* b_out = (const float*)d_in[4];
    float* out = (float*)d_out;

    float* hbuf;  float* fbuf;  int* rbuf;
    cudaGetSymbolAddress((void**)&hbuf, g_h);
    cudaGetSymbolAddress((void**)&fbuf, g_fused);
    cudaGetSymbolAddress((void**)&rbuf, g_routes);

    cudaFuncSetAttribute(attn_kernel, cudaFuncAttributeMaxDynamicSharedMemorySize,
                         ATTN_SMEM_BYTES);

    // 1) normalize routes
    prep_routes_kernel<<<64, 256>>>(rt, rbuf, NS * NK);

    // 2) h = x @ W_in^T
    dim3 gemm_grid(ND / 128, NS / 128);  // (8, 16) = 128 blocks, one wave
    gemm_tf32_kernel<false><<<gemm_grid, 256>>>(x, W_in, hbuf, nullptr, nullptr,
                                                NS, ND, ND);

    // 3) gather attention
    attn_kernel<<<dim3(NS, NH / GH), 128, ATTN_SMEM_BYTES>>>(hbuf, rbuf, fbuf);

    // 4) out = fused @ W_out^T + b_out + x
    gemm_tf32_kernel<true><<<gemm_grid, 256>>>(fbuf, W_out, out, b_out, x,
                                               NS, ND, ND);
}

// round 5
// speedup vs baseline: 1.3333x; 1.0007x over previous
#include <cuda_runtime.h>
#include <cuda_bf16.h>
#include <cstdint>

// Problem constants
#define NS 2048      // sequence length
#define ND 1024      // model dim
#define NH 16        // heads
#define NHD 64       // head dim
#define NK 64        // neighbors per token

// ---------------------------------------------------------------------------
// Scratch (static device allocations — no cudaMalloc allowed)
// ---------------------------------------------------------------------------
__device__ float g_h[NS * ND];        // h = x @ W_in^T
__device__ float g_fused[NS * ND];    // attention output
__device__ int   g_routes[NS * NK];   // normalized int32 routes

// ---------------------------------------------------------------------------
// Route normalization: int64 (reference) or int32 (jax x64 off). Sniff odd
// 32-bit words of the first 512 entries: all zero => int64 little-endian.
// ---------------------------------------------------------------------------
__global__ void prep_routes_kernel(const unsigned* __restrict__ src,
                                   int* __restrict__ dst, int n) {
    int any = 0;
    for (int i = threadIdx.x; i < 512; i += blockDim.x)
        if (src[2 * i + 1] != 0u) any = 1;
    any = __syncthreads_or(any);

    int stride = gridDim.x * blockDim.x;
    int start = blockIdx.x * blockDim.x + threadIdx.x;
    if (any) {
        for (int i = start; i < n; i += stride) dst[i] = (int)src[i];
    } else {
        for (int i = start; i < n; i += stride) dst[i] = (int)src[2 * i];
    }
}

// ---------------------------------------------------------------------------
// MMA + cp.async helpers
// ---------------------------------------------------------------------------
__device__ __forceinline__ void mma_tf32(float* c, const uint32_t* a, const uint32_t* b) {
    asm volatile(
        "mma.sync.aligned.m16n8k8.row.col.f32.tf32.tf32.f32 "
        "{%0,%1,%2,%3}, {%4,%5,%6,%7}, {%8,%9}, {%0,%1,%2,%3};\n"
        : "+f"(c[0]), "+f"(c[1]), "+f"(c[2]), "+f"(c[3])
        : "r"(a[0]), "r"(a[1]), "r"(a[2]), "r"(a[3]),
          "r"(b[0]), "r"(b[1]));
}

__device__ __forceinline__ void cp_async16(void* smem_ptr, const void* gmem_ptr) {
    uint32_t s = (uint32_t)__cvta_generic_to_shared(smem_ptr);
    asm volatile("cp.async.cg.shared.global [%0], [%1], 16;\n" :: "r"(s), "l"(gmem_ptr));
}
__device__ __forceinline__ void cp_commit() {
    asm volatile("cp.async.commit_group;\n");
}
template <int N>
__device__ __forceinline__ void cp_wait() {
    asm volatile("cp.async.wait_group %0;\n" :: "n"(N));
}

// ---------------------------------------------------------------------------
// GEMM: C[M,N] = A[M,Kd] @ B[N,Kd]^T (row-major, K contiguous => row.col MMA)
// EPI: C += bias[n] + resid[m,n]
// BM=BN=128, BK=16. 256 threads = 8 warps (2 x 4), warp tile 64x32
// (4x4 grid of m16n8k8, 2 k-substeps). cp.async 2-stage double buffer.
// Raw fp32 fed to tf32 MMA (HW truncates mantissa; no cvt needed).
// smem row stride 20 floats: 16B-aligned for cp.async, and fragment reads
// (bank = (g*20+t) mod 32 over g=0..7,t=0..3) are conflict-free.
// ---------------------------------------------------------------------------
template <bool EPI>
__global__ __launch_bounds__(256) void gemm_tf32_kernel(
        const float* __restrict__ A, const float* __restrict__ B,
        float* __restrict__ C, const float* __restrict__ bias,
        const float* __restrict__ resid, int M, int N, int Kd) {
    constexpr int BM = 128, BN = 128, BK = 16, LDA = BK + 4;  // 20 floats/row
    __shared__ float As[2][BM * LDA];
    __shared__ float Bs[2][BN * LDA];

    const int tid = threadIdx.x;
    const int w = tid >> 5, l = tid & 31;
    const int wm = w >> 2, wn = w & 3;   // 2 x 4 warp grid
    const int g = l >> 2, t = l & 3;     // groupID, threadInGroup
    const int bm = blockIdx.y * BM, bn = blockIdx.x * BN;

    // staging indices: 512 float4 per matrix per stage, 2 per thread
    const int r0 = (tid + 0) >> 2,   c0 = ((tid + 0) & 3) * 4;
    const int r1 = (tid + 256) >> 2, c1 = ((tid + 256) & 3) * 4;

    float acc[4][4][4];
#pragma unroll
    for (int mi = 0; mi < 4; mi++)
#pragma unroll
        for (int nj = 0; nj < 4; nj++)
#pragma unroll
            for (int q = 0; q < 4; q++) acc[mi][nj][q] = 0.f;

    const int NIT = Kd / BK;  // 64

    // prologue: stage 0
    {
        const int k0 = 0;
        cp_async16(&As[0][r0 * LDA + c0], &A[(size_t)(bm + r0) * Kd + k0 + c0]);
        cp_async16(&As[0][r1 * LDA + c1], &A[(size_t)(bm + r1) * Kd + k0 + c1]);
        cp_async16(&Bs[0][r0 * LDA + c0], &B[(size_t)(bn + r0) * Kd + k0 + c0]);
        cp_async16(&Bs[0][r1 * LDA + c1], &B[(size_t)(bn + r1) * Kd + k0 + c1]);
        cp_commit();
    }

    for (int it = 0; it < NIT; it++) {
        if (it + 1 < NIT) {
            const int k0 = (it + 1) * BK;
            const int st = (it + 1) & 1;
            cp_async16(&As[st][r0 * LDA + c0], &A[(size_t)(bm + r0) * Kd + k0 + c0]);
            cp_async16(&As[st][r1 * LDA + c1], &A[(size_t)(bm + r1) * Kd + k0 + c1]);
            cp_async16(&Bs[st][r0 * LDA + c0], &B[(size_t)(bn + r0) * Kd + k0 + c0]);
            cp_async16(&Bs[st][r1 * LDA + c1], &B[(size_t)(bn + r1) * Kd + k0 + c1]);
            cp_commit();
            cp_wait<1>();
        } else {
            cp_wait<0>();
        }
        __syncthreads();

        const float* as = As[it & 1];
        const float* bs = Bs[it & 1];
#pragma unroll
        for (int kk = 0; kk < BK; kk += 8) {
            uint32_t a[4][4], b[4][2];
#pragma unroll
            for (int mi = 0; mi < 4; mi++) {
                int r = wm * 64 + mi * 16 + g;
                a[mi][0] = __float_as_uint(as[r * LDA + kk + t]);
                a[mi][1] = __float_as_uint(as[(r + 8) * LDA + kk + t]);
                a[mi][2] = __float_as_uint(as[r * LDA + kk + t + 4]);
                a[mi][3] = __float_as_uint(as[(r + 8) * LDA + kk + t + 4]);
            }
#pragma unroll
            for (int nj = 0; nj < 4; nj++) {
                int cc = wn * 32 + nj * 8 + g;
                b[nj][0] = __float_as_uint(bs[cc * LDA + kk + t]);
                b[nj][1] = __float_as_uint(bs[cc * LDA + kk + t + 4]);
            }
#pragma unroll
            for (int mi = 0; mi < 4; mi++)
#pragma unroll
                for (int nj = 0; nj < 4; nj++)
                    mma_tf32(acc[mi][nj], a[mi], b[nj]);
        }
        __syncthreads();   // stage (it&1) gets overwritten at it+2's prefetch
    }

    // Epilogue
#pragma unroll
    for (int mi = 0; mi < 4; mi++) {
#pragma unroll
        for (int nj = 0; nj < 4; nj++) {
            int row = bm + wm * 64 + mi * 16 + g;
            int col = bn + wn * 32 + nj * 8 + 2 * t;
            float v0 = acc[mi][nj][0], v1 = acc[mi][nj][1];
            float v2 = acc[mi][nj][2], v3 = acc[mi][nj][3];
            if (EPI) {
                float b0 = bias[col], b1 = bias[col + 1];
                v0 += b0 + resid[(size_t)row * N + col];
                v1 += b1 + resid[(size_t)row * N + col + 1];
                v2 += b0 + resid[(size_t)(row + 8) * N + col];
                v3 += b1 + resid[(size_t)(row + 8) * N + col + 1];
            }
            *(float2*)&C[(size_t)row * N + col] = make_float2(v0, v1);
            *(float2*)&C[(size_t)(row + 8) * N + col] = make_float2(v2, v3);
        }
    }
}

// ---------------------------------------------------------------------------
// Fused gather-attention (unchanged from R2 — next optimization target,
// kept fixed this round so the GEMM delta is attributable).
// ---------------------------------------------------------------------------
#define GH 4
#define VSTRIDE (GH * NHD + 2)   // 258 floats per k-row
#define ATTN_SMEM_BYTES ((NK * VSTRIDE + GH * NHD + GH * NK) * 4 + NK * 4)

__global__ void attn_kernel(const float* __restrict__ h,
                            const int* __restrict__ routes,
                            float* __restrict__ fused) {
    extern __shared__ float sm[];
    float* vs = sm;                       // [NK][VSTRIDE]
    float* qs = vs + NK * VSTRIDE;        // [GH*NHD]
    float* ws = qs + GH * NHD;            // [GH][NK]
    int* rt = (int*)(ws + GH * NK);       // [NK]

    const int s = blockIdx.x;
    const int g0 = blockIdx.y * GH;
    const int tid = threadIdx.x;
    const int w = tid >> 5, l = tid & 31;

    if (tid < NK) rt[tid] = routes[s * NK + tid];
    {
        const float2* qsrc = (const float2*)(h + (size_t)s * ND + g0 * NHD);
        ((float2*)qs)[tid] = qsrc[tid];
    }
    __syncthreads();

    for (int k = w; k < NK; k += 4) {
        const float4* src = (const float4*)(h + (size_t)rt[k] * ND + g0 * NHD);
        float* dst = vs + k * VSTRIDE;
#pragma unroll
        for (int i = 0; i < 2; i++) {
            float4 v = src[l + 32 * i];
            int d = (l + 32 * i) * 4;
            *(float2*)(dst + d) = make_float2(v.x, v.y);
            *(float2*)(dst + d + 2) = make_float2(v.z, v.w);
        }
    }
    __syncthreads();

    const float* qh = qs + w * NHD;
    const float* v0p = vs + l * VSTRIDE + w * NHD;
    const float* v1p = vs + (l + 32) * VSTRIDE + w * NHD;
    float sc0 = 0.f, sc1 = 0.f;
#pragma unroll
    for (int d = 0; d < NHD; d += 2) {
        float q0 = qh[d], q1 = qh[d + 1];
        float2 a = *(const float2*)(v0p + d);
        float2 b = *(const float2*)(v1p + d);
        sc0 += q0 * a.x + q1 * a.y;
        sc1 += q0 * b.x + q1 * b.y;
    }
    const float scale = 0.125f;
    sc0 *= scale; sc1 *= scale;

    float mx = fmaxf(sc0, sc1);
#pragma unroll
    for (int o = 16; o; o >>= 1) mx = fmaxf(mx, __shfl_xor_sync(0xffffffffu, mx, o));
    float e0 = __expf(sc0 - mx), e1 = __expf(sc1 - mx);
    float sum = e0 + e1;
#pragma unroll
    for (int o = 16; o; o >>= 1) sum += __shfl_xor_sync(0xffffffffu, sum, o);
    float inv = 1.0f / sum;
    ws[w * NK + l] = e0 * inv;
    ws[w * NK + l + 32] = e1 * inv;
    __syncwarp();

    float ax = 0.f, ay = 0.f;
    const float* col = vs + w * NHD + 2 * l;
    const float* wr = ws + w * NK;
#pragma unroll
    for (int k = 0; k < NK; k++) {
        float wk = wr[k];
        float2 v = *(const float2*)(col + k * VSTRIDE);
        ax += wk * v.x;
        ay += wk * v.y;
    }
    *(float2*)(fused + (size_t)s * ND + (g0 + w) * NHD + 2 * l) = make_float2(ax, ay);
}

// ---------------------------------------------------------------------------
// Launch
// ---------------------------------------------------------------------------
extern "C" void kernel_launch(void* const* d_in, const int* in_sizes, int n_in,
                              void* d_out, int out_size) {
    const float* x     = (const float*)d_in[0];
    const unsigned* rt = (const unsigned*)d_in[1];
    const float* W_in  = (const float*)d_in[2];
    const float* W_out = (const float*)d_in[3];
    const float* b_out = (const float*)d_in[4];
    float* out = (float*)d_out;

    float* hbuf;  float* fbuf;  int* rbuf;
    cudaGetSymbolAddress((void**)&hbuf, g_h);
    cudaGetSymbolAddress((void**)&fbuf, g_fused);
    cudaGetSymbolAddress((void**)&rbuf, g_routes);

    cudaFuncSetAttribute(attn_kernel, cudaFuncAttributeMaxDynamicSharedMemorySize,
                         ATTN_SMEM_BYTES);

    // 1) normalize routes
    prep_routes_kernel<<<64, 256>>>(rt, rbuf, NS * NK);

    // 2) h = x @ W_in^T
    dim3 gemm_grid(ND / 128, NS / 128);  // (8, 16) = 128 blocks, one wave
    gemm_tf32_kernel<false><<<gemm_grid, 256>>>(x, W_in, hbuf, nullptr, nullptr,
                                                NS, ND, ND);

    // 3) gather attention
    attn_kernel<<<dim3(NS, NH / GH), 128, ATTN_SMEM_BYTES>>>(hbuf, rbuf, fbuf);

    // 4) out = fused @ W_out^T + b_out + x
    gemm_tf32_kernel<true><<<gemm_grid, 256>>>(fbuf, W_out, out, b_out, x,
                                               NS, ND, ND);
}